// round 8
// baseline (speedup 1.0000x reference)
#include <cuda_runtime.h>
#include <cuda_bf16.h>
#include <cstdint>
#include <math.h>

// ---------------- problem constants ----------------
#define N_IMG 2
#define R_TOT 159882
#define N_LVL 5
#define POST_NMS 1000
#define NMS_THRESH 0.7f
#define IMG_MAX 800.0f
#define MIN_SIZE 1e-3f
#define BBOX_CLIP 4.135166556742356f   // log(1000/16) rounded to f32
#define MAXBLK 30                      // histogram/collect blocks for largest level

__constant__ int c_loff[N_LVL]  = {0, 120000, 150000, 157500, 159375};
__constant__ int c_lsize[N_LVL] = {120000, 30000, 7500, 1875, 507};
__constant__ int c_ksel[N_LVL]  = {1000, 1000, 1000, 1000, 507};
__constant__ int c_soff[N_LVL]  = {0, 1000, 2000, 3000, 4000};
__constant__ int c_nblk[N_LVL]  = {30, 8, 2, 1, 1};

// ---------------- scratch (device globals; no allocation allowed) ----------
__device__ unsigned           g_hist_part[N_IMG * N_LVL * MAXBLK * 2048];
__device__ unsigned           g_prefix[N_IMG * N_LVL];
__device__ unsigned           g_pmask [N_IMG * N_LVL];
__device__ unsigned           g_kth   [N_IMG * N_LVL];
__device__ int                g_ccnt[N_IMG * N_LVL];
__device__ unsigned long long g_coll[N_IMG * N_LVL * 2048];
// per (img,level) compacted NMS candidate lists:
__device__ int                g_ncnt[N_IMG * N_LVL];
__device__ float4             g_nbox [N_IMG * N_LVL * 1024];  // OFFSET boxes
__device__ float              g_narea[N_IMG * N_LVL * 1024];
__device__ unsigned long long g_nkey [N_IMG * N_LVL * 1024];
__device__ int                g_npos [N_IMG * N_LVL * 1024];  // within-level p
// raw (unoffset) boxes + scores indexed by within-level p:
__device__ float4             g_rawbox[N_IMG * N_LVL * 1024];
__device__ float              g_rawsc [N_IMG * N_LVL * 1024];
// suppression bit-matrix, layout [il][w*1024 + i]:
__device__ unsigned           g_mask[N_IMG * N_LVL * 32 * 1024];
// kept lists (key-descending):
__device__ unsigned long long g_kept_key[N_IMG * N_LVL * 1024];
__device__ int                g_kept_p  [N_IMG * N_LVL * 1024];
__device__ int                g_kept_cnt[N_IMG * N_LVL];

// ---------------- helpers ----------------
__device__ __forceinline__ unsigned mono_key(float f) {
    unsigned u = __float_as_uint(f);
    return (u & 0x80000000u) ? ~u : (u | 0x80000000u);
}
__device__ __forceinline__ float mono_inv(unsigned m) {
    unsigned u = (m & 0x80000000u) ? (m & 0x7fffffffu) : ~m;
    return __uint_as_float(u);
}

// block-wide ordered compaction scan (1024 threads)
__device__ __forceinline__ int block_scan_flag(bool flag, int* total) {
    __shared__ int wsum[32];
    int lane = threadIdx.x & 31;
    int wid  = threadIdx.x >> 5;
    unsigned ballot = __ballot_sync(0xffffffffu, flag);
    int lane_pref = __popc(ballot & ((1u << lane) - 1u));
    if (lane == 0) wsum[wid] = __popc(ballot);
    __syncthreads();
    if (wid == 0) {
        int v = wsum[lane];
        #pragma unroll
        for (int d = 1; d < 32; d <<= 1) {
            int x = __shfl_up_sync(0xffffffffu, v, d);
            if (lane >= d) v += x;
        }
        wsum[lane] = v;
    }
    __syncthreads();
    int excl = (wid == 0 ? 0 : wsum[wid - 1]) + lane_pref;
    *total = wsum[31];
    __syncthreads();
    return excl;
}

// ============ K-hist: grid-parallel histogram for one radix pass ==============
__global__ void hist_kernel(const float* __restrict__ obj,
                            int shift, int bins, int first) {
    const int il  = blockIdx.y;
    const int lvl = il % N_LVL;
    const int img = il / N_LVL;
    const int nblk = c_nblk[lvl];
    const int b = blockIdx.x;
    if (b >= nblk) return;
    const int n = c_lsize[lvl];
    const int chunk = (n + nblk - 1) / nblk;
    const int i0 = b * chunk;
    const int i1 = min(i0 + chunk, n);
    const int tid = threadIdx.x;
    const unsigned bm = (unsigned)bins - 1u;
    const unsigned prefix = first ? 0u : g_prefix[il];
    const unsigned pmask  = first ? 0u : g_pmask[il];

    __shared__ unsigned h[2048];
    for (int t = tid; t < bins; t += 256) h[t] = 0;
    __syncthreads();
    const float* src = obj + img * R_TOT + c_loff[lvl];
    for (int i = i0 + tid; i < i1; i += 256) {
        unsigned u = mono_key(src[i]);
        if ((u & pmask) == prefix) atomicAdd(&h[(u >> shift) & bm], 1u);
    }
    __syncthreads();
    unsigned* out = &g_hist_part[(il * MAXBLK + b) * 2048];
    for (int t = tid; t < bins; t += 256) out[t] = h[t];
}

// ============ K-select: sum partials, suffix-scan, pick boundary bucket =======
__global__ void select_kernel(int shift, int bins, int first, int last) {
    const int il  = blockIdx.x;
    const int lvl = il % N_LVL;
    const int nblk = c_nblk[lvl];
    const int tid  = threadIdx.x;
    const int lane = tid & 31;
    const int wrp  = tid >> 5;
    const unsigned kth = first ? (unsigned)c_ksel[lvl] : g_kth[il];

    __shared__ unsigned wtot[32], wtot2[32];
    __shared__ unsigned sh_bstar, sh_kth;

    const int bin0 = 2 * tid, bin1 = 2 * tid + 1;
    unsigned e0 = 0, e1 = 0;
    if (bin0 < bins) {
        for (int b = 0; b < nblk; ++b) {
            const unsigned* hp = &g_hist_part[(il * MAXBLK + b) * 2048];
            e0 += hp[bin0];
            if (bin1 < bins) e1 += hp[bin1];
        }
    }
    unsigned s = e0 + e1;
    unsigned S = s;
    #pragma unroll
    for (int d = 1; d < 32; d <<= 1) {
        unsigned x = __shfl_down_sync(0xffffffffu, S, d);
        if (lane + d < 32) S += x;
    }
    if (lane == 0) wtot[wrp] = S;
    __syncthreads();
    if (wrp == 0) {
        unsigned W = wtot[lane];
        #pragma unroll
        for (int d = 1; d < 32; d <<= 1) {
            unsigned x = __shfl_down_sync(0xffffffffu, W, d);
            if (lane + d < 32) W += x;
        }
        wtot2[lane] = W;
    }
    __syncthreads();
    unsigned after_warp = (wrp < 31) ? wtot2[wrp + 1] : 0u;
    unsigned sfx_after = (S - s) + after_warp;   // suffix strictly after pair
    unsigned sfx1 = e1 + sfx_after;
    unsigned sfx0 = s + sfx_after;
    if (bin0 < bins && sfx0 >= kth && sfx1 < kth) { sh_bstar = (unsigned)bin0; sh_kth = kth - sfx1; }
    if (bin1 < bins && sfx1 >= kth && sfx_after < kth) { sh_bstar = (unsigned)bin1; sh_kth = kth - sfx_after; }
    __syncthreads();
    if (tid == 0) {
        const unsigned bm = (unsigned)bins - 1u;
        unsigned pref = (first ? 0u : g_prefix[il]) | (sh_bstar << shift);
        unsigned pm   = (first ? 0u : g_pmask[il])  | (bm << shift);
        g_prefix[il] = pref;
        g_pmask[il]  = pm;
        g_kth[il]    = sh_kth;
        if (last) g_ccnt[il] = 0;    // prefix now == exact threshold T
    }
}

// ============ K-collect: grid-parallel collection of candidates >= T ==========
__global__ void collect_kernel(const float* __restrict__ obj) {
    const int il  = blockIdx.y;
    const int lvl = il % N_LVL;
    const int img = il / N_LVL;
    const int nblk = c_nblk[lvl];
    const int b = blockIdx.x;
    if (b >= nblk) return;
    const int n = c_lsize[lvl];
    const int chunk = (n + nblk - 1) / nblk;
    const int i0 = b * chunk;
    const int i1 = min(i0 + chunk, n);
    const int tid = threadIdx.x;
    const unsigned T = g_prefix[il];   // exact mono key of k-th largest

    const float* src = obj + img * R_TOT + c_loff[lvl];
    for (int i = i0 + tid; i < i1; i += 256) {
        unsigned u = mono_key(src[i]);
        if (u >= T) {
            int p = atomicAdd(&g_ccnt[il], 1);
            if (p < 2048)
                g_coll[il * 2048 + p] = ((unsigned long long)u << 17) | (unsigned)(131071 - i);
        }
    }
}

// ============ K3: per-il sort + decode + compact ==============================
__global__ void sortdecode_kernel(const float* __restrict__ deltas,
                                  const float* __restrict__ anchors,
                                  float* __restrict__ out) {
    const int il  = blockIdx.x;
    const int img = il / N_LVL;
    const int lvl = il % N_LVL;
    const int base = c_loff[lvl];
    const int k    = c_ksel[lvl];
    const int tid  = threadIdx.x;

    __shared__ unsigned long long skey[2048];

    // default-fill outputs (once per image; lvl==0 block)
    if (lvl == 0) {
        float* ob = out + img * (POST_NMS * 4);
        float* os = out + N_IMG * POST_NMS * 4 + img * POST_NMS;
        for (int x = tid; x < POST_NMS * 4; x += 1024) ob[x] = 0.0f;
        for (int x = tid; x < POST_NMS; x += 1024) os[x] = -1.0f;
    }

    const int csel = min(g_ccnt[il], 2048);
    for (int t = tid; t < 2048; t += 1024)
        skey[t] = (t < csel) ? g_coll[il * 2048 + t] : 0ull;
    __syncthreads();

    // size-adaptive bitonic sort ascending
    int sortN = 512;
    while (sortN < csel) sortN <<= 1;
    const int npairs = sortN >> 1;
    for (int k2 = 2; k2 <= sortN; k2 <<= 1) {
        for (int j = k2 >> 1; j > 0; j >>= 1) {
            if (tid < npairs) {
                int i2 = ((tid & ~(j - 1)) << 1) | (tid & (j - 1));
                int p2 = i2 + j;
                bool dir = ((i2 & k2) == 0);
                unsigned long long A = skey[i2], B = skey[p2];
                if ((A > B) == dir) { skey[i2] = B; skey[p2] = A; }
            }
            __syncthreads();
        }
    }

    // decode candidate p = tid (objectness recovered from the sort key)
    bool flag = false;
    float4 obox = make_float4(0.f, 0.f, 0.f, 0.f);
    float area = 0.f, score = 0.f;
    if (tid < k) {
        unsigned long long kk = skey[sortN - 1 - tid];
        int i = 131071 - (int)(kk & 0x1FFFFull);
        int r = base + i;
        const float o = mono_inv((unsigned)(kk >> 17));
        score = __fdiv_rn(1.0f, __fadd_rn(1.0f, expf(-o)));

        float4 a = *(const float4*)(anchors + 4 * r);
        const float wa = __fsub_rn(a.z, a.x);
        const float ha = __fsub_rn(a.w, a.y);
        const float cxa = __fadd_rn(a.x, __fmul_rn(0.5f, wa));
        const float cya = __fadd_rn(a.y, __fmul_rn(0.5f, ha));

        float4 d = *(const float4*)(deltas + (size_t)(img * R_TOT + r) * 4);
        const float dw = fminf(d.z, BBOX_CLIP);
        const float dh = fminf(d.w, BBOX_CLIP);
        const float cx = __fadd_rn(__fmul_rn(d.x, wa), cxa);
        const float cy = __fadd_rn(__fmul_rn(d.y, ha), cya);
        const float w = __fmul_rn(expf(dw), wa);
        const float h = __fmul_rn(expf(dh), ha);

        float x1 = __fsub_rn(cx, __fmul_rn(0.5f, w));
        float y1 = __fsub_rn(cy, __fmul_rn(0.5f, h));
        float x2 = __fadd_rn(cx, __fmul_rn(0.5f, w));
        float y2 = __fadd_rn(cy, __fmul_rn(0.5f, h));
        x1 = fminf(fmaxf(x1, 0.0f), IMG_MAX);
        y1 = fminf(fmaxf(y1, 0.0f), IMG_MAX);
        x2 = fminf(fmaxf(x2, 0.0f), IMG_MAX);
        y2 = fminf(fmaxf(y2, 0.0f), IMG_MAX);

        flag = (__fsub_rn(x2, x1) >= MIN_SIZE) &&
               (__fsub_rn(y2, y1) >= MIN_SIZE) &&
               (score >= 0.0f);
        g_rawbox[il * 1024 + tid] = make_float4(x1, y1, x2, y2);
        g_rawsc [il * 1024 + tid] = score;

        const float off = (float)lvl * 801.0f;
        float ox1 = __fadd_rn(x1, off);
        float oy1 = __fadd_rn(y1, off);
        float ox2 = __fadd_rn(x2, off);
        float oy2 = __fadd_rn(y2, off);
        obox = make_float4(ox1, oy1, ox2, oy2);
        area = __fmul_rn(__fsub_rn(ox2, ox1), __fsub_rn(oy2, oy1));
    }
    int m;
    int pos = block_scan_flag(flag, &m);
    if (flag) {
        const int gb = il * 1024 + pos;
        g_nbox [gb] = obox;
        g_narea[gb] = area;
        const int gpos = c_soff[lvl] + tid;   // global candidate position
        g_nkey [gb] = ((unsigned long long)mono_key(score) << 13) | (unsigned)(8191 - gpos);
        g_npos [gb] = tid;
    }
    if (tid == 0) g_ncnt[il] = m;
}

// ============ K4: suppression bit-matrix build (massively parallel) ==========
__global__ void build_kernel() {
    __shared__ float4 sbox[1024];
    __shared__ float  sarea[1024];
    const int il = blockIdx.y;
    const int b  = blockIdx.x;
    const int tid = threadIdx.x;
    const int lane = tid & 31;
    const int wrp  = tid >> 5;

    const int m = g_ncnt[il];
    for (int i = tid; i < m; i += 256) {
        sbox[i]  = g_nbox [il * 1024 + i];
        sarea[i] = g_narea[il * 1024 + i];
    }
    __syncthreads();

    const int nchunks = (m + 31) >> 5;
    unsigned* mbase = &g_mask[il * 32768];

    for (int i = b * 8 + wrp; i < m; i += 256) {
        const float4 bi = sbox[i];
        const float ai = sarea[i];
        for (int w = i >> 5; w < nchunks; ++w) {
            const int j = (w << 5) + lane;
            bool sup = false;
            if (j > i && j < m) {
                float4 bj = sbox[j];
                float lx = fmaxf(bi.x, bj.x), ly = fmaxf(bi.y, bj.y);
                float rx = fminf(bi.z, bj.z), ry = fminf(bi.w, bj.w);
                float wx = fmaxf(__fsub_rn(rx, lx), 0.0f);
                float wy = fmaxf(__fsub_rn(ry, ly), 0.0f);
                float inter = __fmul_rn(wx, wy);
                if (inter > 0.0f) {
                    float denom = __fadd_rn(__fsub_rn(__fadd_rn(ai, sarea[j]), inter), 1e-9f);
                    float iou = __fdiv_rn(inter, denom);
                    sup = iou > NMS_THRESH;
                }
            }
            unsigned bits = __ballot_sync(0xffffffffu, sup);
            if (lane == 0) mbase[w * 1024 + i] = bits;
        }
    }
}

// ============ K5: chunked greedy resolve (mask read once, straight from L2) ==
__global__ void resolve_kernel() {
    __shared__ unsigned ssup[32];
    __shared__ unsigned skept[32];
    const int il = blockIdx.x;
    const int tid = threadIdx.x;
    const int lane = tid & 31;
    const int wrp  = tid >> 5;

    const int m = g_ncnt[il];
    const int nchunks = (m + 31) >> 5;
    const unsigned* mbase = &g_mask[il * 32768];

    if (tid < 32) { ssup[tid] = 0u; skept[tid] = 0u; }
    __syncthreads();

    for (int c = 0; c < nchunks; ++c) {
        if (tid == 0) {
            unsigned diag[32];
            const unsigned* dp = mbase + c * 1024 + (c << 5);
            #pragma unroll
            for (int j = 0; j < 32; ++j) diag[j] = dp[j];
            unsigned sup = ssup[c];
            unsigned kept = 0u;
            const int jmax = min(32, m - (c << 5));
            for (int j = 0; j < jmax; ++j) {
                if (!((sup >> j) & 1u)) {
                    kept |= 1u << j;
                    sup |= diag[j];
                }
            }
            skept[c] = kept;
        }
        __syncthreads();
        const int wfut = c + 1 + wrp;
        if (wfut < nchunks) {
            unsigned kept = skept[c];
            unsigned v = ((kept >> lane) & 1u) ? mbase[wfut * 1024 + (c << 5) + lane] : 0u;
            unsigned red = __reduce_or_sync(0xffffffffu, v);
            if (lane == 0) ssup[wfut] |= red;
        }
        __syncthreads();
    }

    bool kflag = (tid < m) && ((skept[tid >> 5] >> (tid & 31)) & 1u);
    int mkept;
    int kpos = block_scan_flag(kflag, &mkept);
    if (kflag) {
        g_kept_key[il * 1024 + kpos] = g_nkey[il * 1024 + tid];
        g_kept_p  [il * 1024 + kpos] = g_npos[il * 1024 + tid];
    }
    if (tid == 0) g_kept_cnt[il] = mkept;
}

// ============ K6: merge-rank kept lists + write outputs =======================
__global__ void out_kernel(float* __restrict__ out) {
    __shared__ unsigned long long skeys[N_LVL * 1024];   // 40KB
    __shared__ int cnt[N_LVL];
    const int il = blockIdx.x;
    const int img = il / N_LVL;
    const int L   = il % N_LVL;
    const int tid = threadIdx.x;
    float* out_b = out + img * (POST_NMS * 4);
    float* out_s = out + N_IMG * POST_NMS * 4 + img * POST_NMS;

    if (tid < N_LVL) cnt[tid] = g_kept_cnt[img * N_LVL + tid];
    __syncthreads();
    for (int l = 0; l < N_LVL; ++l)
        for (int i = tid; i < cnt[l]; i += 1024)
            skeys[l * 1024 + i] = g_kept_key[(img * N_LVL + l) * 1024 + i];
    __syncthreads();

    const int myc = cnt[L];
    for (int i = tid; i < myc; i += 1024) {
        const unsigned long long key = skeys[L * 1024 + i];
        int rank = i;
        #pragma unroll
        for (int L2 = 0; L2 < N_LVL; ++L2) {
            if (L2 == L) continue;
            const unsigned long long* a = &skeys[L2 * 1024];
            int lo = 0, hi = cnt[L2];
            while (lo < hi) {
                int mid = (lo + hi) >> 1;
                if (a[mid] > key) lo = mid + 1; else hi = mid;
            }
            rank += lo;
        }
        if (rank < POST_NMS) {
            const int p = g_kept_p[il * 1024 + i];
            float4 bx = g_rawbox[il * 1024 + p];
            out_b[rank * 4 + 0] = bx.x;
            out_b[rank * 4 + 1] = bx.y;
            out_b[rank * 4 + 2] = bx.z;
            out_b[rank * 4 + 3] = bx.w;
            out_s[rank] = g_rawsc[il * 1024 + p];
        }
    }
}

// ---------------- launch -----------------------------------------------------
extern "C" void kernel_launch(void* const* d_in, const int* in_sizes, int n_in,
                              void* d_out, int out_size) {
    const float* objectness = (const float*)d_in[0];   // [2, 159882]
    const float* deltas     = (const float*)d_in[1];   // [2, 159882, 4]
    const float* anchors    = (const float*)d_in[2];   // [159882, 4]
    float* out = (float*)d_out;                        // boxes [2,1000,4] ++ scores [2,1000]

    const dim3 hgrid(MAXBLK, N_IMG * N_LVL);
    // pass 0: bits[31:21]
    hist_kernel<<<hgrid, 256>>>(objectness, 21, 2048, 1);
    select_kernel<<<N_IMG * N_LVL, 1024>>>(21, 2048, 1, 0);
    // pass 1: bits[20:10]
    hist_kernel<<<hgrid, 256>>>(objectness, 10, 2048, 0);
    select_kernel<<<N_IMG * N_LVL, 1024>>>(10, 2048, 0, 0);
    // pass 2: bits[9:0]
    hist_kernel<<<hgrid, 256>>>(objectness, 0, 1024, 0);
    select_kernel<<<N_IMG * N_LVL, 1024>>>(0, 1024, 0, 1);

    collect_kernel<<<hgrid, 256>>>(objectness);
    sortdecode_kernel<<<N_IMG * N_LVL, 1024>>>(deltas, anchors, out);
    build_kernel<<<dim3(32, N_IMG * N_LVL), 256>>>();
    resolve_kernel<<<N_IMG * N_LVL, 1024>>>();
    out_kernel<<<N_IMG * N_LVL, 1024>>>(out);
}

// round 9
// speedup vs baseline: 1.0944x; 1.0944x over previous
#include <cuda_runtime.h>
#include <cuda_bf16.h>
#include <cstdint>
#include <math.h>

// ---------------- problem constants ----------------
#define N_IMG 2
#define R_TOT 159882
#define N_LVL 5
#define POST_NMS 1000
#define NMS_THRESH 0.7f
#define IMG_MAX 800.0f
#define MIN_SIZE 1e-3f
#define BBOX_CLIP 4.135166556742356f   // log(1000/16) rounded to f32
#define MAXBLK 30                      // histogram/collect blocks for largest level

__constant__ int c_loff[N_LVL]  = {0, 120000, 150000, 157500, 159375};
__constant__ int c_lsize[N_LVL] = {120000, 30000, 7500, 1875, 507};
__constant__ int c_ksel[N_LVL]  = {1000, 1000, 1000, 1000, 507};
__constant__ int c_soff[N_LVL]  = {0, 1000, 2000, 3000, 4000};
__constant__ int c_nblk[N_LVL]  = {30, 8, 2, 1, 1};

// ---------------- scratch (device globals; zero-initialized at load) --------
__device__ unsigned           g_hist[N_IMG * N_LVL * 2048];   // zeroed by last block each pass
__device__ int                g_arrive[N_IMG * N_LVL];        // ticket; reset by last block
__device__ unsigned           g_prefix[N_IMG * N_LVL];
__device__ unsigned           g_pmask [N_IMG * N_LVL];
__device__ unsigned           g_kth   [N_IMG * N_LVL];
__device__ int                g_ccnt[N_IMG * N_LVL];
__device__ unsigned long long g_coll[N_IMG * N_LVL * 2048];
// per (img,level) compacted NMS candidate lists:
__device__ int                g_ncnt[N_IMG * N_LVL];
__device__ float4             g_nbox [N_IMG * N_LVL * 1024];  // OFFSET boxes
__device__ float              g_narea[N_IMG * N_LVL * 1024];
__device__ unsigned long long g_nkey [N_IMG * N_LVL * 1024];
__device__ int                g_npos [N_IMG * N_LVL * 1024];  // within-level p
// raw (unoffset) boxes + scores indexed by within-level p:
__device__ float4             g_rawbox[N_IMG * N_LVL * 1024];
__device__ float              g_rawsc [N_IMG * N_LVL * 1024];
// suppression bit-matrix, layout [il][w*1024 + i]:
__device__ unsigned           g_mask[N_IMG * N_LVL * 32 * 1024];
// kept lists (key-descending):
__device__ unsigned long long g_kept_key[N_IMG * N_LVL * 1024];
__device__ int                g_kept_p  [N_IMG * N_LVL * 1024];
__device__ int                g_kept_cnt[N_IMG * N_LVL];

// ---------------- helpers ----------------
__device__ __forceinline__ unsigned mono_key(float f) {
    unsigned u = __float_as_uint(f);
    return (u & 0x80000000u) ? ~u : (u | 0x80000000u);
}
__device__ __forceinline__ float mono_inv(unsigned m) {
    unsigned u = (m & 0x80000000u) ? (m & 0x7fffffffu) : ~m;
    return __uint_as_float(u);
}

// block-wide ordered compaction scan (1024 threads)
__device__ __forceinline__ int block_scan_flag(bool flag, int* total) {
    __shared__ int wsum[32];
    int lane = threadIdx.x & 31;
    int wid  = threadIdx.x >> 5;
    unsigned ballot = __ballot_sync(0xffffffffu, flag);
    int lane_pref = __popc(ballot & ((1u << lane) - 1u));
    if (lane == 0) wsum[wid] = __popc(ballot);
    __syncthreads();
    if (wid == 0) {
        int v = wsum[lane];
        #pragma unroll
        for (int d = 1; d < 32; d <<= 1) {
            int x = __shfl_up_sync(0xffffffffu, v, d);
            if (lane >= d) v += x;
        }
        wsum[lane] = v;
    }
    __syncthreads();
    int excl = (wid == 0 ? 0 : wsum[wid - 1]) + lane_pref;
    *total = wsum[31];
    __syncthreads();
    return excl;
}

// ============ K-histsel: grid-parallel histogram + last-block select ==========
// 11-bit pass. All blocks add their smem hist into g_hist[il]; the LAST block
// (atomic ticket) reads+zeroes g_hist, suffix-scans, picks the boundary bucket,
// and updates g_prefix/g_pmask/g_kth (and resets g_ccnt on the last pass).
__global__ void histsel_kernel(const float* __restrict__ obj,
                               int shift, int first, int last) {
    const int il  = blockIdx.y;
    const int lvl = il % N_LVL;
    const int img = il / N_LVL;
    const int nblk = c_nblk[lvl];
    const int b = blockIdx.x;
    if (b >= nblk) return;
    const int n = c_lsize[lvl];
    const int chunk = (n + nblk - 1) / nblk;
    const int i0 = b * chunk;
    const int i1 = min(i0 + chunk, n);
    const int tid  = threadIdx.x;      // 256 threads
    const int lane = tid & 31;
    const int wrp  = tid >> 5;
    const unsigned prefix = first ? 0u : g_prefix[il];
    const unsigned pmask  = first ? 0u : g_pmask[il];

    __shared__ unsigned h[2048];
    for (int t = tid; t < 2048; t += 256) h[t] = 0;
    __syncthreads();
    const float* src = obj + img * R_TOT + c_loff[lvl];
    for (int i = i0 + tid; i < i1; i += 256) {
        unsigned u = mono_key(src[i]);
        if ((u & pmask) == prefix) atomicAdd(&h[(u >> shift) & 2047u], 1u);
    }
    __syncthreads();
    unsigned* gh = &g_hist[il * 2048];
    for (int t = tid; t < 2048; t += 256)
        if (h[t]) atomicAdd(&gh[t], h[t]);
    __threadfence();

    __shared__ int s_last;
    if (tid == 0) {
        int ticket = atomicAdd(&g_arrive[il], 1);
        s_last = (ticket == nblk - 1);
        if (s_last) g_arrive[il] = 0;            // reset for next pass / replay
    }
    __syncthreads();
    if (!s_last) return;

    // ---- last block: select boundary bucket (256 threads x 8 bins each) ----
    __shared__ unsigned wtot[8];
    __shared__ unsigned after_w[8];
    __shared__ unsigned sh_bstar, sh_kth;
    const unsigned kth = first ? (unsigned)c_ksel[lvl] : g_kth[il];

    unsigned e[8];
    const int base = tid * 8;
    #pragma unroll
    for (int j = 0; j < 8; ++j) { e[j] = gh[base + j]; gh[base + j] = 0u; }
    unsigned s = 0;
    #pragma unroll
    for (int j = 0; j < 8; ++j) s += e[j];
    // warp suffix (inclusive from this lane)
    unsigned S = s;
    #pragma unroll
    for (int d = 1; d < 32; d <<= 1) {
        unsigned x = __shfl_down_sync(0xffffffffu, S, d);
        if (lane + d < 32) S += x;
    }
    if (lane == 0) wtot[wrp] = S;
    __syncthreads();
    if (tid < 8) {
        unsigned a = 0;
        for (int ww = tid + 1; ww < 8; ++ww) a += wtot[ww];
        after_w[tid] = a;
    }
    __syncthreads();
    const unsigned sfx_after = (S - s) + after_w[wrp];  // suffix strictly after my 8 bins
    // walk own bins high->low maintaining running suffix
    unsigned suf = sfx_after;
    #pragma unroll
    for (int j = 7; j >= 0; --j) {
        unsigned sufnext = suf;       // suffix(base+j+1)
        suf += e[j];                  // suffix(base+j)
        if (suf >= kth && sufnext < kth) {
            sh_bstar = (unsigned)(base + j);
            sh_kth   = kth - sufnext;
        }
    }
    __syncthreads();
    if (tid == 0) {
        g_prefix[il] = prefix | (sh_bstar << shift);
        g_pmask[il]  = pmask  | (2047u << shift);
        g_kth[il]    = sh_kth;
        if (last) g_ccnt[il] = 0;
    }
}

// ============ K-collect: grid-parallel collection of candidates >= T ==========
// T = 22-bit prefix << 10 : collects a SUPERSET of the top-k (all elements
// above the boundary bucket + the whole boundary bucket, ~k+5 elements).
// The downstream full-key sort extracts the exact top-k.
__global__ void collect_kernel(const float* __restrict__ obj) {
    const int il  = blockIdx.y;
    const int lvl = il % N_LVL;
    const int img = il / N_LVL;
    const int nblk = c_nblk[lvl];
    const int b = blockIdx.x;
    if (b >= nblk) return;
    const int n = c_lsize[lvl];
    const int chunk = (n + nblk - 1) / nblk;
    const int i0 = b * chunk;
    const int i1 = min(i0 + chunk, n);
    const int tid = threadIdx.x;
    const unsigned T = g_prefix[il];

    const float* src = obj + img * R_TOT + c_loff[lvl];
    for (int i = i0 + tid; i < i1; i += 256) {
        unsigned u = mono_key(src[i]);
        if (u >= T) {
            int p = atomicAdd(&g_ccnt[il], 1);
            if (p < 2048)
                g_coll[il * 2048 + p] = ((unsigned long long)u << 17) | (unsigned)(131071 - i);
        }
    }
}

// ============ K3: per-il sort + decode + compact ==============================
__global__ void sortdecode_kernel(const float* __restrict__ deltas,
                                  const float* __restrict__ anchors,
                                  float* __restrict__ out) {
    const int il  = blockIdx.x;
    const int img = il / N_LVL;
    const int lvl = il % N_LVL;
    const int base = c_loff[lvl];
    const int k    = c_ksel[lvl];
    const int tid  = threadIdx.x;

    __shared__ unsigned long long skey[2048];

    // default-fill outputs (once per image; lvl==0 block)
    if (lvl == 0) {
        float* ob = out + img * (POST_NMS * 4);
        float* os = out + N_IMG * POST_NMS * 4 + img * POST_NMS;
        for (int x = tid; x < POST_NMS * 4; x += 1024) ob[x] = 0.0f;
        for (int x = tid; x < POST_NMS; x += 1024) os[x] = -1.0f;
    }

    const int csel = min(g_ccnt[il], 2048);
    for (int t = tid; t < 2048; t += 1024)
        skey[t] = (t < csel) ? g_coll[il * 2048 + t] : 0ull;
    __syncthreads();

    // size-adaptive bitonic sort ascending
    int sortN = 512;
    while (sortN < csel) sortN <<= 1;
    const int npairs = sortN >> 1;
    for (int k2 = 2; k2 <= sortN; k2 <<= 1) {
        for (int j = k2 >> 1; j > 0; j >>= 1) {
            if (tid < npairs) {
                int i2 = ((tid & ~(j - 1)) << 1) | (tid & (j - 1));
                int p2 = i2 + j;
                bool dir = ((i2 & k2) == 0);
                unsigned long long A = skey[i2], B = skey[p2];
                if ((A > B) == dir) { skey[i2] = B; skey[p2] = A; }
            }
            __syncthreads();
        }
    }

    // decode candidate p = tid (objectness recovered from the sort key)
    bool flag = false;
    float4 obox = make_float4(0.f, 0.f, 0.f, 0.f);
    float area = 0.f, score = 0.f;
    if (tid < k) {
        unsigned long long kk = skey[sortN - 1 - tid];
        int i = 131071 - (int)(kk & 0x1FFFFull);
        int r = base + i;
        const float o = mono_inv((unsigned)(kk >> 17));
        score = __fdiv_rn(1.0f, __fadd_rn(1.0f, expf(-o)));

        float4 a = *(const float4*)(anchors + 4 * r);
        const float wa = __fsub_rn(a.z, a.x);
        const float ha = __fsub_rn(a.w, a.y);
        const float cxa = __fadd_rn(a.x, __fmul_rn(0.5f, wa));
        const float cya = __fadd_rn(a.y, __fmul_rn(0.5f, ha));

        float4 d = *(const float4*)(deltas + (size_t)(img * R_TOT + r) * 4);
        const float dw = fminf(d.z, BBOX_CLIP);
        const float dh = fminf(d.w, BBOX_CLIP);
        const float cx = __fadd_rn(__fmul_rn(d.x, wa), cxa);
        const float cy = __fadd_rn(__fmul_rn(d.y, ha), cya);
        const float w = __fmul_rn(expf(dw), wa);
        const float h = __fmul_rn(expf(dh), ha);

        float x1 = __fsub_rn(cx, __fmul_rn(0.5f, w));
        float y1 = __fsub_rn(cy, __fmul_rn(0.5f, h));
        float x2 = __fadd_rn(cx, __fmul_rn(0.5f, w));
        float y2 = __fadd_rn(cy, __fmul_rn(0.5f, h));
        x1 = fminf(fmaxf(x1, 0.0f), IMG_MAX);
        y1 = fminf(fmaxf(y1, 0.0f), IMG_MAX);
        x2 = fminf(fmaxf(x2, 0.0f), IMG_MAX);
        y2 = fminf(fmaxf(y2, 0.0f), IMG_MAX);

        flag = (__fsub_rn(x2, x1) >= MIN_SIZE) &&
               (__fsub_rn(y2, y1) >= MIN_SIZE) &&
               (score >= 0.0f);
        g_rawbox[il * 1024 + tid] = make_float4(x1, y1, x2, y2);
        g_rawsc [il * 1024 + tid] = score;

        const float off = (float)lvl * 801.0f;
        float ox1 = __fadd_rn(x1, off);
        float oy1 = __fadd_rn(y1, off);
        float ox2 = __fadd_rn(x2, off);
        float oy2 = __fadd_rn(y2, off);
        obox = make_float4(ox1, oy1, ox2, oy2);
        area = __fmul_rn(__fsub_rn(ox2, ox1), __fsub_rn(oy2, oy1));
    }
    int m;
    int pos = block_scan_flag(flag, &m);
    if (flag) {
        const int gb = il * 1024 + pos;
        g_nbox [gb] = obox;
        g_narea[gb] = area;
        const int gpos = c_soff[lvl] + tid;   // global candidate position
        g_nkey [gb] = ((unsigned long long)mono_key(score) << 13) | (unsigned)(8191 - gpos);
        g_npos [gb] = tid;
    }
    if (tid == 0) g_ncnt[il] = m;
}

// ============ K4: suppression bit-matrix build (massively parallel) ==========
__global__ void build_kernel() {
    __shared__ float4 sbox[1024];
    __shared__ float  sarea[1024];
    const int il = blockIdx.y;
    const int b  = blockIdx.x;
    const int tid = threadIdx.x;
    const int lane = tid & 31;
    const int wrp  = tid >> 5;

    const int m = g_ncnt[il];
    for (int i = tid; i < m; i += 256) {
        sbox[i]  = g_nbox [il * 1024 + i];
        sarea[i] = g_narea[il * 1024 + i];
    }
    __syncthreads();

    const int nchunks = (m + 31) >> 5;
    unsigned* mbase = &g_mask[il * 32768];

    for (int i = b * 8 + wrp; i < m; i += 256) {
        const float4 bi = sbox[i];
        const float ai = sarea[i];
        for (int w = i >> 5; w < nchunks; ++w) {
            const int j = (w << 5) + lane;
            bool sup = false;
            if (j > i && j < m) {
                float4 bj = sbox[j];
                float lx = fmaxf(bi.x, bj.x), ly = fmaxf(bi.y, bj.y);
                float rx = fminf(bi.z, bj.z), ry = fminf(bi.w, bj.w);
                float wx = fmaxf(__fsub_rn(rx, lx), 0.0f);
                float wy = fmaxf(__fsub_rn(ry, ly), 0.0f);
                float inter = __fmul_rn(wx, wy);
                if (inter > 0.0f) {
                    float denom = __fadd_rn(__fsub_rn(__fadd_rn(ai, sarea[j]), inter), 1e-9f);
                    float iou = __fdiv_rn(inter, denom);
                    sup = iou > NMS_THRESH;
                }
            }
            unsigned bits = __ballot_sync(0xffffffffu, sup);
            if (lane == 0) mbase[w * 1024 + i] = bits;
        }
    }
}

// ============ K5: chunked greedy resolve (mask read once, straight from L2) ==
__global__ void resolve_kernel() {
    __shared__ unsigned ssup[32];
    __shared__ unsigned skept[32];
    const int il = blockIdx.x;
    const int tid = threadIdx.x;
    const int lane = tid & 31;
    const int wrp  = tid >> 5;

    const int m = g_ncnt[il];
    const int nchunks = (m + 31) >> 5;
    const unsigned* mbase = &g_mask[il * 32768];

    if (tid < 32) { ssup[tid] = 0u; skept[tid] = 0u; }
    __syncthreads();

    for (int c = 0; c < nchunks; ++c) {
        if (tid == 0) {
            unsigned diag[32];
            const unsigned* dp = mbase + c * 1024 + (c << 5);
            #pragma unroll
            for (int j = 0; j < 32; ++j) diag[j] = dp[j];
            unsigned sup = ssup[c];
            unsigned kept = 0u;
            const int jmax = min(32, m - (c << 5));
            for (int j = 0; j < jmax; ++j) {
                if (!((sup >> j) & 1u)) {
                    kept |= 1u << j;
                    sup |= diag[j];
                }
            }
            skept[c] = kept;
        }
        __syncthreads();
        const int wfut = c + 1 + wrp;
        if (wfut < nchunks) {
            unsigned kept = skept[c];
            unsigned v = ((kept >> lane) & 1u) ? mbase[wfut * 1024 + (c << 5) + lane] : 0u;
            unsigned red = __reduce_or_sync(0xffffffffu, v);
            if (lane == 0) ssup[wfut] |= red;
        }
        __syncthreads();
    }

    bool kflag = (tid < m) && ((skept[tid >> 5] >> (tid & 31)) & 1u);
    int mkept;
    int kpos = block_scan_flag(kflag, &mkept);
    if (kflag) {
        g_kept_key[il * 1024 + kpos] = g_nkey[il * 1024 + tid];
        g_kept_p  [il * 1024 + kpos] = g_npos[il * 1024 + tid];
    }
    if (tid == 0) g_kept_cnt[il] = mkept;
}

// ============ K6: merge-rank kept lists + write outputs =======================
__global__ void out_kernel(float* __restrict__ out) {
    __shared__ unsigned long long skeys[N_LVL * 1024];   // 40KB
    __shared__ int cnt[N_LVL];
    const int il = blockIdx.x;
    const int img = il / N_LVL;
    const int L   = il % N_LVL;
    const int tid = threadIdx.x;
    float* out_b = out + img * (POST_NMS * 4);
    float* out_s = out + N_IMG * POST_NMS * 4 + img * POST_NMS;

    if (tid < N_LVL) cnt[tid] = g_kept_cnt[img * N_LVL + tid];
    __syncthreads();
    for (int l = 0; l < N_LVL; ++l)
        for (int i = tid; i < cnt[l]; i += 1024)
            skeys[l * 1024 + i] = g_kept_key[(img * N_LVL + l) * 1024 + i];
    __syncthreads();

    const int myc = cnt[L];
    for (int i = tid; i < myc; i += 1024) {
        const unsigned long long key = skeys[L * 1024 + i];
        int rank = i;
        #pragma unroll
        for (int L2 = 0; L2 < N_LVL; ++L2) {
            if (L2 == L) continue;
            const unsigned long long* a = &skeys[L2 * 1024];
            int lo = 0, hi = cnt[L2];
            while (lo < hi) {
                int mid = (lo + hi) >> 1;
                if (a[mid] > key) lo = mid + 1; else hi = mid;
            }
            rank += lo;
        }
        if (rank < POST_NMS) {
            const int p = g_kept_p[il * 1024 + i];
            float4 bx = g_rawbox[il * 1024 + p];
            out_b[rank * 4 + 0] = bx.x;
            out_b[rank * 4 + 1] = bx.y;
            out_b[rank * 4 + 2] = bx.z;
            out_b[rank * 4 + 3] = bx.w;
            out_s[rank] = g_rawsc[il * 1024 + p];
        }
    }
}

// ---------------- launch -----------------------------------------------------
extern "C" void kernel_launch(void* const* d_in, const int* in_sizes, int n_in,
                              void* d_out, int out_size) {
    const float* objectness = (const float*)d_in[0];   // [2, 159882]
    const float* deltas     = (const float*)d_in[1];   // [2, 159882, 4]
    const float* anchors    = (const float*)d_in[2];   // [159882, 4]
    float* out = (float*)d_out;                        // boxes [2,1000,4] ++ scores [2,1000]

    const dim3 hgrid(MAXBLK, N_IMG * N_LVL);
    histsel_kernel<<<hgrid, 256>>>(objectness, 21, 1, 0);   // bits[31:21]
    histsel_kernel<<<hgrid, 256>>>(objectness, 10, 0, 1);   // bits[20:10]
    collect_kernel<<<hgrid, 256>>>(objectness);
    sortdecode_kernel<<<N_IMG * N_LVL, 1024>>>(deltas, anchors, out);
    build_kernel<<<dim3(32, N_IMG * N_LVL), 256>>>();
    resolve_kernel<<<N_IMG * N_LVL, 1024>>>();
    out_kernel<<<N_IMG * N_LVL, 1024>>>(out);
}